// round 13
// baseline (speedup 1.0000x reference)
#include <cuda_runtime.h>
#include <cuda_fp16.h>

#define D 128
#define MAX_N 100000
#define MBLK 64            // rows of x per GEMM block
#define PADH 136           // GEMM smem row stride in halves

// Aggregation tile constants
#define SPAD 136           // S row stride in halves (272B: conflict-free LDSM)
#define APAD 72            // A row stride in halves (word-stride 36 -> 4g+tig)
#define S_BYTES (64 * SPAD * 2)            // 17408
#define A_BYTES (16 * APAD * 2)            // 2304
#define SRC_BYTES (64 * 4)                 // 256
#define WSM (S_BYTES + A_BYTES + SRC_BYTES) // 19968 bytes per warp

// support = x@W + b, stored fp16 (25.6 MB)
__device__ __half g_support_h[(size_t)MAX_N * D];
// W transposed + converted to fp16: Wt[n][k]
__device__ __half g_Wt_h[D * D];
// CSR row pointers for destination nodes
__device__ int g_rowptr[MAX_N + 1];

// ---------------------------------------------------------------------------
// prep: Wt_h[n][k] = fp16(W[k][n])
// ---------------------------------------------------------------------------
__global__ void prep_kernel(const float* __restrict__ W, __half* __restrict__ Wt) {
    int i = blockIdx.x * blockDim.x + threadIdx.x;
    if (i < D * D) {
        int k = i >> 7, n = i & 127;
        Wt[n * D + k] = __float2half(W[i]);
    }
}

// ---------------------------------------------------------------------------
// rowptr: edst sorted -> rp[d] = first edge with dst >= d. O(E+N).
// ---------------------------------------------------------------------------
__global__ void rowptr_kernel(const int* __restrict__ edst,
                              int* __restrict__ rp, int E, int N) {
    int e = blockIdx.x * blockDim.x + threadIdx.x;
    if (e >= E) return;
    int d  = edst[e];
    int dp = (e == 0) ? -1 : edst[e - 1];
    for (int k = dp + 1; k <= d; k++) rp[k] = e;
    if (e == E - 1)
        for (int k = d + 1; k <= N; k++) rp[k] = E;
}

__device__ __forceinline__ void mma_f16(float d[4], unsigned a0, unsigned a1,
                                        unsigned a2, unsigned a3,
                                        unsigned b0, unsigned b1) {
    asm volatile(
        "mma.sync.aligned.m16n8k16.row.col.f32.f16.f16.f32 "
        "{%0,%1,%2,%3}, {%4,%5,%6,%7}, {%8,%9}, {%0,%1,%2,%3};"
        : "+f"(d[0]), "+f"(d[1]), "+f"(d[2]), "+f"(d[3])
        : "r"(a0), "r"(a1), "r"(a2), "r"(a3), "r"(b0), "r"(b1));
}

__device__ __forceinline__ void ldsm_x4_trans(unsigned& r0, unsigned& r1,
                                              unsigned& r2, unsigned& r3,
                                              unsigned addr) {
    asm volatile(
        "ldmatrix.sync.aligned.m8n8.x4.trans.shared.b16 {%0,%1,%2,%3}, [%4];"
        : "=r"(r0), "=r"(r1), "=r"(r2), "=r"(r3) : "r"(addr));
}

// ---------------------------------------------------------------------------
// GEMM: support = fp16(x@W + b) via fp16 mma m16n8k16. (Memory-floor bound;
// unchanged from the proven R10 kernel.)
// ---------------------------------------------------------------------------
__global__ void __launch_bounds__(256) gemm_mma_kernel(
        const float* __restrict__ x,
        const __half* __restrict__ Wt,
        const float* __restrict__ b,
        __half* __restrict__ sup, int N) {
    extern __shared__ __half smem[];
    __half* sX = smem;                 // 64  x PADH halves
    __half* sW = smem + MBLK * PADH;   // 128 x PADH halves ([n][k])

    const int tid  = threadIdx.x;
    const int lane = tid & 31;
    const int w    = tid >> 5;
    const int wm   = w & 3;
    const int wn   = w >> 2;
    const int g    = lane >> 2;
    const int tig  = lane & 3;

    const int row0 = blockIdx.x * MBLK;

    const uint4* Wv = (const uint4*)Wt;
    #pragma unroll
    for (int i = tid; i < 128 * 16; i += 256) {
        int r = i >> 4, c = i & 15;
        *(uint4*)(sW + r * PADH + c * 8) = Wv[i];
    }
    const float4* xv = (const float4*)x;
    #pragma unroll
    for (int i = tid; i < MBLK * 32; i += 256) {
        int r = i >> 5, c = i & 31;
        float4 v = make_float4(0.f, 0.f, 0.f, 0.f);
        if (row0 + r < N) v = xv[(size_t)(row0 + r) * 32 + c];
        __half2 h0 = __floats2half2_rn(v.x, v.y);
        __half2 h1 = __floats2half2_rn(v.z, v.w);
        uint2 p = make_uint2(*(unsigned*)&h0, *(unsigned*)&h1);
        *(uint2*)(sX + r * PADH + c * 4) = p;
    }
    __syncthreads();

    float acc[8][4];
    #pragma unroll
    for (int t = 0; t < 8; t++)
        #pragma unroll
        for (int j = 0; j < 4; j++) acc[t][j] = 0.f;

    const int ar0 = wm * 16 + g;
    const int ar1 = ar0 + 8;

    #pragma unroll
    for (int k0 = 0; k0 < D; k0 += 16) {
        unsigned a0 = *(const unsigned*)(sX + ar0 * PADH + k0 + 2 * tig);
        unsigned a1 = *(const unsigned*)(sX + ar1 * PADH + k0 + 2 * tig);
        unsigned a2 = *(const unsigned*)(sX + ar0 * PADH + k0 + 2 * tig + 8);
        unsigned a3 = *(const unsigned*)(sX + ar1 * PADH + k0 + 2 * tig + 8);
        #pragma unroll
        for (int t = 0; t < 8; t++) {
            int n0 = wn * 64 + t * 8;
            unsigned b0 = *(const unsigned*)(sW + (n0 + g) * PADH + k0 + 2 * tig);
            unsigned b1 = *(const unsigned*)(sW + (n0 + g) * PADH + k0 + 2 * tig + 8);
            mma_f16(acc[t], a0, a1, a2, a3, b0, b1);
        }
    }

    const int gr0 = row0 + wm * 16 + g;
    const int gr1 = gr0 + 8;
    #pragma unroll
    for (int t = 0; t < 8; t++) {
        int col = wn * 64 + t * 8 + 2 * tig;
        float bx = b[col], by = b[col + 1];
        if (gr0 < N) {
            __half2 h = __floats2half2_rn(acc[t][0] + bx, acc[t][1] + by);
            *(__half2*)(sup + (size_t)gr0 * D + col) = h;
        }
        if (gr1 < N) {
            __half2 h = __floats2half2_rn(acc[t][2] + bx, acc[t][3] + by);
            *(__half2*)(sup + (size_t)gr1 * D + col) = h;
        }
    }
}

// ---------------------------------------------------------------------------
// Tensor-core SpMM aggregation. One warp = 16 consecutive dst nodes (their
// edges are contiguous since edst is sorted). Per 64-edge tile:
//   - gather 64 support rows -> smem S[64][SPAD] (coop LDG.128 + STS.128)
//   - build A[16][APAD] fp16: A[dst-base][j] = w_j (zeroed, pad edges w=0)
//   - acc[16x128] += A(16x64) @ S(64x128) via mma.m16n8k16
// A-frags: direct LDS (proven GEMM pattern). B-frags: ldmatrix.x4.trans on
// row-major S. No atomics; every out row written exactly once.
// ---------------------------------------------------------------------------
__global__ void __launch_bounds__(128) scatter_mma_kernel(
        const __half* __restrict__ sup,
        const float* __restrict__ ew,
        const int* __restrict__ esrc,
        const int* __restrict__ edst,
        const int* __restrict__ rp,
        float* __restrict__ out, int N) {
    extern __shared__ char sm_raw[];
    const int wid  = threadIdx.x >> 5;
    const int lane = threadIdx.x & 31;

    char* wbase = sm_raw + wid * WSM;
    __half* Smem = (__half*)wbase;
    __half* Amem = (__half*)(wbase + S_BYTES);
    int*    sSrc = (int*)(wbase + S_BYTES + A_BYTES);

    const int ngroups = (N + 15) / 16;
    const int group = blockIdx.x * 4 + wid;
    if (group >= ngroups) return;

    const int base_node = group * 16;
    const int hi_node   = min(base_node + 16, N);
    const int e0 = rp[base_node];
    const int e1 = rp[hi_node];

    const int g   = lane >> 2;      // 0..7
    const int tig = lane & 3;       // 0..3

    float acc[16][4];
    #pragma unroll
    for (int t = 0; t < 16; t++)
        #pragma unroll
        for (int j = 0; j < 4; j++) acc[t][j] = 0.f;

    const uint4* supv = (const uint4*)sup;
    const unsigned Sbase_u32 = (unsigned)__cvta_generic_to_shared(Smem);

    // per-lane LDSM row/col (constant across tiles)
    const int krow_off = lane & 15;             // k row within 16
    const int ncol_off = (lane >> 4) << 3;      // 0 or 8

    for (int t0 = e0; t0 < e1; t0 += 64) {
        const int tlen = min(64, e1 - t0);

        __syncwarp();   // prev tile's LDSM reads done before overwriting S/A

        // zero A (144 uint4)
        uint4* Au = (uint4*)Amem;
        #pragma unroll
        for (int i = lane; i < A_BYTES / 16; i += 32)
            Au[i] = make_uint4(0u, 0u, 0u, 0u);
        __syncwarp();

        // metadata: srcs to smem, weights into A
        #pragma unroll
        for (int h = 0; h < 2; h++) {
            const int j = lane + h * 32;
            const bool act = (j < tlen);
            int src = 0;
            if (act) {
                const int idx = t0 + j;
                src = esrc[idx];
                const float w = ew[idx];
                const int   row = edst[idx] - base_node;   // in [0,16)
                Amem[row * APAD + j] = __float2half(w);
            }
            sSrc[j] = src;
        }
        __syncwarp();

        // gather 64 rows (padded rows read row 0: valid data, A column is 0)
        #pragma unroll 4
        for (int r = 0; r < 32; r++) {
            const int row = 2 * r + (lane >> 4);
            const int src = sSrc[row];
            const uint4 v = supv[(size_t)src * 16 + (lane & 15)];
            *(uint4*)(Smem + row * SPAD + (lane & 15) * 8) = v;
        }
        __syncwarp();

        // acc += A @ S
        #pragma unroll
        for (int ks = 0; ks < 4; ks++) {
            const int k0 = ks * 16;
            const unsigned a0 = *(const unsigned*)(Amem + g * APAD + k0 + 2 * tig);
            const unsigned a1 = *(const unsigned*)(Amem + (g + 8) * APAD + k0 + 2 * tig);
            const unsigned a2 = *(const unsigned*)(Amem + g * APAD + k0 + 8 + 2 * tig);
            const unsigned a3 = *(const unsigned*)(Amem + (g + 8) * APAD + k0 + 8 + 2 * tig);
            const int krow = k0 + krow_off;
            #pragma unroll
            for (int ng = 0; ng < 8; ng++) {
                const int n0 = ng * 16 + ncol_off;
                unsigned b0, b1, b2, b3;
                ldsm_x4_trans(b0, b1, b2, b3,
                              Sbase_u32 + (unsigned)(krow * SPAD + n0) * 2u);
                mma_f16(acc[ng * 2],     a0, a1, a2, a3, b0, b1);
                mma_f16(acc[ng * 2 + 1], a0, a1, a2, a3, b2, b3);
            }
        }
    }

    // epilogue: store 16x128 accumulator
    const int r0 = base_node + (lane >> 2);
    const int r1 = r0 + 8;
    #pragma unroll
    for (int t = 0; t < 16; t++) {
        const int col = t * 8 + 2 * (lane & 3);
        if (r0 < N)
            *(float2*)(out + (size_t)r0 * D + col) = make_float2(acc[t][0], acc[t][1]);
        if (r1 < N)
            *(float2*)(out + (size_t)r1 * D + col) = make_float2(acc[t][2], acc[t][3]);
    }
}

extern "C" void kernel_launch(void* const* d_in, const int* in_sizes, int n_in,
                              void* d_out, int out_size) {
    const float* x    = (const float*)d_in[0];
    const float* W    = (const float*)d_in[1];
    const float* b    = (const float*)d_in[2];
    const float* ew   = (const float*)d_in[3];
    const int*   esrc = (const int*)d_in[4];
    const int*   edst = (const int*)d_in[5];
    float* out = (float*)d_out;

    const int N = in_sizes[0] / D;
    const int E = in_sizes[3];

    __half* sup = nullptr;
    cudaGetSymbolAddress((void**)&sup, g_support_h);
    __half* Wt = nullptr;
    cudaGetSymbolAddress((void**)&Wt, g_Wt_h);
    int* rp = nullptr;
    cudaGetSymbolAddress((void**)&rp, g_rowptr);

    prep_kernel<<<(D * D + 255) / 256, 256>>>(W, Wt);
    rowptr_kernel<<<(E + 255) / 256, 256>>>(edst, rp, E, N);

    const int gemm_smem = (MBLK * PADH + D * PADH) * (int)sizeof(__half); // ~52 KB
    cudaFuncSetAttribute(gemm_mma_kernel, cudaFuncAttributeMaxDynamicSharedMemorySize, gemm_smem);

    const int gemm_blocks = (N + MBLK - 1) / MBLK;
    gemm_mma_kernel<<<gemm_blocks, 256, gemm_smem>>>(x, Wt, b, sup, N);

    // scatter: 4 warps per block, one 16-node group per warp
    const int ngroups = (N + 15) / 16;
    const int scat_blocks = (ngroups + 3) / 4;
    const int scat_smem = 4 * WSM;   // ~80 KB
    cudaFuncSetAttribute(scatter_mma_kernel, cudaFuncAttributeMaxDynamicSharedMemorySize, scat_smem);
    scatter_mma_kernel<<<scat_blocks, 128, scat_smem>>>(sup, ew, esrc, edst, rp, out, N);
}

// round 14
// speedup vs baseline: 3.8858x; 3.8858x over previous
#include <cuda_runtime.h>
#include <cuda_fp16.h>

#define D 128
#define MAX_N 100000
#define MAX_E 3200000
#define MBLK 64            // rows of x per GEMM block
#define PADH 136           // smem row stride in halves

// support = x@W + b, stored fp16 (25.6 MB)
__device__ __half g_support_h[(size_t)MAX_N * D];
// W transposed + converted to fp16: Wt[n][k]
__device__ __half g_Wt_h[D * D];
// CSR row pointers for destination nodes
__device__ int g_rowptr[MAX_N + 1];
// packed per-edge metadata: (src, weight bits) — one LDG.64 in the scatter
__device__ int2 g_pack[MAX_E];

// ---------------------------------------------------------------------------
// prep: Wt_h[n][k] = fp16(W[k][n])
// ---------------------------------------------------------------------------
__global__ void prep_kernel(const float* __restrict__ W, __half* __restrict__ Wt) {
    int i = blockIdx.x * blockDim.x + threadIdx.x;
    if (i < D * D) {
        int k = i >> 7, n = i & 127;
        Wt[n * D + k] = __float2half(W[i]);
    }
}

// ---------------------------------------------------------------------------
// edge prep: rowptr (edst sorted -> rp[d] = first edge with dst >= d) and
// packed (src, w) metadata, in one pass over E.
// ---------------------------------------------------------------------------
__global__ void edge_prep_kernel(const int* __restrict__ edst,
                                 const int* __restrict__ esrc,
                                 const float* __restrict__ ew,
                                 int* __restrict__ rp,
                                 int2* __restrict__ pk, int E, int N) {
    int e = blockIdx.x * blockDim.x + threadIdx.x;
    if (e >= E) return;
    pk[e] = make_int2(esrc[e], __float_as_int(ew[e]));
    int d  = edst[e];
    int dp = (e == 0) ? -1 : edst[e - 1];
    for (int k = dp + 1; k <= d; k++) rp[k] = e;
    if (e == E - 1)
        for (int k = d + 1; k <= N; k++) rp[k] = E;
}

__device__ __forceinline__ void mma_f16(float d[4], unsigned a0, unsigned a1,
                                        unsigned a2, unsigned a3,
                                        unsigned b0, unsigned b1) {
    asm volatile(
        "mma.sync.aligned.m16n8k16.row.col.f32.f16.f16.f32 "
        "{%0,%1,%2,%3}, {%4,%5,%6,%7}, {%8,%9}, {%0,%1,%2,%3};"
        : "+f"(d[0]), "+f"(d[1]), "+f"(d[2]), "+f"(d[3])
        : "r"(a0), "r"(a1), "r"(a2), "r"(a3), "r"(b0), "r"(b1));
}

// ---------------------------------------------------------------------------
// GEMM: support = fp16(x@W + b) via fp16 mma m16n8k16. (Memory-floor bound;
// unchanged from the proven R10 kernel.)
// ---------------------------------------------------------------------------
__global__ void __launch_bounds__(256) gemm_mma_kernel(
        const float* __restrict__ x,
        const __half* __restrict__ Wt,
        const float* __restrict__ b,
        __half* __restrict__ sup, int N) {
    extern __shared__ __half smem[];
    __half* sX = smem;                 // 64  x PADH halves
    __half* sW = smem + MBLK * PADH;   // 128 x PADH halves ([n][k])

    const int tid  = threadIdx.x;
    const int lane = tid & 31;
    const int w    = tid >> 5;
    const int wm   = w & 3;
    const int wn   = w >> 2;
    const int g    = lane >> 2;
    const int tig  = lane & 3;

    const int row0 = blockIdx.x * MBLK;

    const uint4* Wv = (const uint4*)Wt;
    #pragma unroll
    for (int i = tid; i < 128 * 16; i += 256) {
        int r = i >> 4, c = i & 15;
        *(uint4*)(sW + r * PADH + c * 8) = Wv[i];
    }
    const float4* xv = (const float4*)x;
    #pragma unroll
    for (int i = tid; i < MBLK * 32; i += 256) {
        int r = i >> 5, c = i & 31;
        float4 v = make_float4(0.f, 0.f, 0.f, 0.f);
        if (row0 + r < N) v = xv[(size_t)(row0 + r) * 32 + c];
        __half2 h0 = __floats2half2_rn(v.x, v.y);
        __half2 h1 = __floats2half2_rn(v.z, v.w);
        uint2 p = make_uint2(*(unsigned*)&h0, *(unsigned*)&h1);
        *(uint2*)(sX + r * PADH + c * 4) = p;
    }
    __syncthreads();

    float acc[8][4];
    #pragma unroll
    for (int t = 0; t < 8; t++)
        #pragma unroll
        for (int j = 0; j < 4; j++) acc[t][j] = 0.f;

    const int ar0 = wm * 16 + g;
    const int ar1 = ar0 + 8;

    #pragma unroll
    for (int k0 = 0; k0 < D; k0 += 16) {
        unsigned a0 = *(const unsigned*)(sX + ar0 * PADH + k0 + 2 * tig);
        unsigned a1 = *(const unsigned*)(sX + ar1 * PADH + k0 + 2 * tig);
        unsigned a2 = *(const unsigned*)(sX + ar0 * PADH + k0 + 2 * tig + 8);
        unsigned a3 = *(const unsigned*)(sX + ar1 * PADH + k0 + 2 * tig + 8);
        #pragma unroll
        for (int t = 0; t < 8; t++) {
            int n0 = wn * 64 + t * 8;
            unsigned b0 = *(const unsigned*)(sW + (n0 + g) * PADH + k0 + 2 * tig);
            unsigned b1 = *(const unsigned*)(sW + (n0 + g) * PADH + k0 + 2 * tig + 8);
            mma_f16(acc[t], a0, a1, a2, a3, b0, b1);
        }
    }

    const int gr0 = row0 + wm * 16 + g;
    const int gr1 = gr0 + 8;
    #pragma unroll
    for (int t = 0; t < 8; t++) {
        int col = wn * 64 + t * 8 + 2 * tig;
        float bx = b[col], by = b[col + 1];
        if (gr0 < N) {
            __half2 h = __floats2half2_rn(acc[t][0] + bx, acc[t][1] + by);
            *(__half2*)(sup + (size_t)gr0 * D + col) = h;
        }
        if (gr1 < N) {
            __half2 h = __floats2half2_rn(acc[t][2] + bx, acc[t][3] + by);
            *(__half2*)(sup + (size_t)gr1 * D + col) = h;
        }
    }
}

// ---------------------------------------------------------------------------
// CSR pull: one warp per destination node (R10 champion structure).
// Metadata now one warp-uniform LDG.64 (packed src+w) instead of two LDG.32.
// Lane owns 4 features (uint2 gather). No shfl, no atomics; one STG.128 per
// lane per node.
// ---------------------------------------------------------------------------
__global__ void __launch_bounds__(256) scatter_csr_kernel(
        const __half* __restrict__ sup,
        const int2* __restrict__ pk,
        const int* __restrict__ rp,
        float* __restrict__ out, int N) {
    const int warp = (blockIdx.x * blockDim.x + threadIdx.x) >> 5;
    const int lane = threadIdx.x & 31;
    if (warp >= N) return;

    const int beg = rp[warp];
    const int end = rp[warp + 1];

    const uint2* supv = (const uint2*)sup;
    float4 acc = make_float4(0.f, 0.f, 0.f, 0.f);

    #pragma unroll 4
    for (int e = beg; e < end; e++) {
        const int2 p = __ldg(pk + e);          // warp-uniform LDG.64
        const float w = __int_as_float(p.y);
        uint2 u = supv[(size_t)p.x * 32 + lane];
        float2 f0 = __half22float2(*(__half2*)(&u.x));
        float2 f1 = __half22float2(*(__half2*)(&u.y));
        acc.x += w * f0.x; acc.y += w * f0.y;
        acc.z += w * f1.x; acc.w += w * f1.y;
    }

    *(float4*)(out + (size_t)warp * D + lane * 4) = acc;
}

extern "C" void kernel_launch(void* const* d_in, const int* in_sizes, int n_in,
                              void* d_out, int out_size) {
    const float* x    = (const float*)d_in[0];
    const float* W    = (const float*)d_in[1];
    const float* b    = (const float*)d_in[2];
    const float* ew   = (const float*)d_in[3];
    const int*   esrc = (const int*)d_in[4];
    const int*   edst = (const int*)d_in[5];
    float* out = (float*)d_out;

    const int N = in_sizes[0] / D;
    const int E = in_sizes[3];

    __half* sup = nullptr;
    cudaGetSymbolAddress((void**)&sup, g_support_h);
    __half* Wt = nullptr;
    cudaGetSymbolAddress((void**)&Wt, g_Wt_h);
    int* rp = nullptr;
    cudaGetSymbolAddress((void**)&rp, g_rowptr);
    int2* pk = nullptr;
    cudaGetSymbolAddress((void**)&pk, g_pack);

    prep_kernel<<<(D * D + 255) / 256, 256>>>(W, Wt);
    edge_prep_kernel<<<(E + 255) / 256, 256>>>(edst, esrc, ew, rp, pk, E, N);

    const int gemm_smem = (MBLK * PADH + D * PADH) * (int)sizeof(__half); // ~52 KB
    cudaFuncSetAttribute(gemm_mma_kernel, cudaFuncAttributeMaxDynamicSharedMemorySize, gemm_smem);

    const int gemm_blocks = (N + MBLK - 1) / MBLK;
    gemm_mma_kernel<<<gemm_blocks, 256, gemm_smem>>>(x, Wt, b, sup, N);

    // one warp per node, 8 warps per block
    const int scat_blocks = (N + 7) / 8;
    scatter_csr_kernel<<<scat_blocks, 256>>>(sup, pk, rp, out, N);
}